// round 6
// baseline (speedup 1.0000x reference)
#include <cuda_runtime.h>
#include <cuda_bf16.h>
#include <math.h>

#define BATCH 4096
#define NNB   64
#define DM    256
#define NH    8
#define HD    32
#define SCALE 0.17677669529663687f   // 1/sqrt(32)

// ---------------- scratch ----------------
__device__ float d_Q  [BATCH * DM];
__device__ float d_U  [BATCH * NH * DM];
__device__ float d_ctx[BATCH * NH * DM];
__device__ float d_att[BATCH * DM];
__device__ float d_y  [BATCH * DM];
__device__ float d_WkT[NH * DM * HD];      // [h][c][d]
__device__ float d_WoT[DM * DM];
__device__ float d_Wc [DM * DM];
__device__ float d_b1 [DM];
__device__ unsigned int d_or = 0u;         // OR of odd words; 0 => int64

// ---------------- prep: transposes + b1 + edge-dtype detect ----------------
__global__ void prep_kernel(const float* __restrict__ Wk,
                            const float* __restrict__ Wo,
                            const float* __restrict__ Wf,
                            const float* __restrict__ bo,
                            const float* __restrict__ bfv,
                            const unsigned int* __restrict__ e32) {
    const int blk = blockIdx.x, t = threadIdx.x;
    const int i = blk * 256 + t;                 // 0..65535
    { int dd = i & 31, c = (i >> 5) & 255, h = i >> 13;
      d_WkT[i] = Wk[(h * HD + dd) * DM + c]; }
    { int j = i >> 8, m = i & 255;
      d_WoT[i] = Wo[m * DM + j]; }
    if (blk < 32) {
        int o = blk * 8 + (t >> 5), l = t & 31;
        float s = 0.f;
        #pragma unroll
        for (int m = l; m < DM; m += 32) s += Wf[o * 2 * DM + m] * bo[m];
        #pragma unroll
        for (int off = 16; off; off >>= 1) s += __shfl_xor_sync(0xffffffffu, s, off);
        if (l == 0) d_b1[o] = bfv[o] + s;
    }
    unsigned int acc = 0u;
    #pragma unroll
    for (int w = i; w < BATCH * NNB; w += 65536) acc |= e32[2 * w + 1];
    #pragma unroll
    for (int o = 16; o; o >>= 1) acc |= __shfl_xor_sync(0xffffffffu, acc, o);
    __shared__ unsigned int sOr;
    if (t == 0) sOr = 0u;
    __syncthreads();
    if ((t & 31) == 0 && acc) atomicOr(&sOr, acc);
    __syncthreads();
    if (t == 0 && sOr) atomicOr(&d_or, sOr);
}

// ---------------- dedicated U GEMM (K=32 single pass) ----------------
__global__ __launch_bounds__(256) void ugemm_kernel() {
    __shared__ float As[HD][132];
    __shared__ float Bs[HD][132];
    const int t = threadIdx.x;
    const int tx = t & 15, ty = t >> 4;
    const int b0 = blockIdx.y * 128;
    const int c0 = blockIdx.x * 128;
    const int h  = blockIdx.z;

    #pragma unroll
    for (int i = 0; i < 4; i++) {
        int f = t + i * 256;
        int r = f >> 3, dq = f & 7;
        float4 v = *reinterpret_cast<const float4*>(d_Q + (long)(b0 + r) * DM + h * HD + dq * 4);
        As[dq * 4 + 0][r] = v.x; As[dq * 4 + 1][r] = v.y;
        As[dq * 4 + 2][r] = v.z; As[dq * 4 + 3][r] = v.w;
    }
    #pragma unroll
    for (int i = 0; i < 4; i++) {
        int f = t + i * 256;
        int c = f >> 3, dq = f & 7;
        float4 v = *reinterpret_cast<const float4*>(d_WkT + h * (DM * HD) + (c0 + c) * HD + dq * 4);
        Bs[dq * 4 + 0][c] = v.x; Bs[dq * 4 + 1][c] = v.y;
        Bs[dq * 4 + 2][c] = v.z; Bs[dq * 4 + 3][c] = v.w;
    }
    __syncthreads();

    float acc[8][8];
    #pragma unroll
    for (int i = 0; i < 8; i++)
        #pragma unroll
        for (int j = 0; j < 8; j++) acc[i][j] = 0.f;

    #pragma unroll
    for (int d = 0; d < HD; d++) {
        float a[8], b[8];
        #pragma unroll
        for (int i = 0; i < 8; i++) a[i] = As[d][ty + 16 * i];
        #pragma unroll
        for (int j = 0; j < 8; j++) b[j] = Bs[d][tx + 16 * j];
        #pragma unroll
        for (int i = 0; i < 8; i++)
            #pragma unroll
            for (int j = 0; j < 8; j++) acc[i][j] += a[i] * b[j];
    }

    #pragma unroll
    for (int i = 0; i < 8; i++) {
        long base = (long)(b0 + ty + 16 * i) * (NH * DM) + h * DM + c0;
        #pragma unroll
        for (int j = 0; j < 8; j++)
            d_U[base + tx + 16 * j] = SCALE * acc[i][j];
    }
}

// ---------------- double-buffered NT GEMM with optional dual K-source -------
template<int BM, int BN, int TM, int TN>
__global__ void gemm2_kernel(const float* __restrict__ A1, int lda1, long az1,
                             const float* __restrict__ B1, int ldb1, long bz1,
                             const float* __restrict__ A2, int lda2,
                             const float* __restrict__ B2, int ldb2,
                             const float* __restrict__ bias, long biasz,
                             float* __restrict__ C, int ldc, long cz,
                             int K1, int Ktot, float alpha) {
    constexpr int BK = 16;
    constexpr int NT = (BM / TM) * (BN / TN);
    constexpr int PAD = 4;
    constexpr int A4 = BM * BK / 4;
    constexpr int B4 = BN * BK / 4;
    constexpr int NA = (A4 + NT - 1) / NT;
    constexpr int NB = (B4 + NT - 1) / NT;

    __shared__ float As[2][BK][BM + PAD];
    __shared__ float Bs[2][BK][BN + PAD];

    const int tid = threadIdx.x;
    const int tx = tid % (BN / TN);
    const int ty = tid / (BN / TN);
    const int row0 = blockIdx.y * BM;
    const int col0 = blockIdx.x * BN;
    const int z = blockIdx.z;

    const float* A1g = A1 + (long)z * az1;
    const float* B1g = B1 + (long)z * bz1;
    float* Cg = C + (long)z * cz;
    const float* biasg = bias ? bias + (long)z * biasz : nullptr;

    float4 ra[NA], rb[NB];

    auto fetch = [&](int t) {
        int k0 = t * BK;
        const float *Ap, *Bp; int lda, ldb, k;
        if (k0 < K1) { Ap = A1g; lda = lda1; Bp = B1g; ldb = ldb1; k = k0; }
        else         { Ap = A2;  lda = lda2; Bp = B2;  ldb = ldb2; k = k0 - K1; }
        #pragma unroll
        for (int i = 0; i < NA; i++) {
            int f = tid + i * NT;
            if (f < A4) {
                int r = f >> 2, kq = f & 3;
                ra[i] = *reinterpret_cast<const float4*>(Ap + (long)(row0 + r) * lda + k + kq * 4);
            }
        }
        #pragma unroll
        for (int i = 0; i < NB; i++) {
            int f = tid + i * NT;
            if (f < B4) {
                int n = f >> 2, kq = f & 3;
                rb[i] = *reinterpret_cast<const float4*>(Bp + (long)(col0 + n) * ldb + k + kq * 4);
            }
        }
    };
    auto stage = [&](int buf) {
        #pragma unroll
        for (int i = 0; i < NA; i++) {
            int f = tid + i * NT;
            if (f < A4) {
                int r = f >> 2, kq = f & 3;
                As[buf][kq * 4 + 0][r] = ra[i].x;
                As[buf][kq * 4 + 1][r] = ra[i].y;
                As[buf][kq * 4 + 2][r] = ra[i].z;
                As[buf][kq * 4 + 3][r] = ra[i].w;
            }
        }
        #pragma unroll
        for (int i = 0; i < NB; i++) {
            int f = tid + i * NT;
            if (f < B4) {
                int n = f >> 2, kq = f & 3;
                Bs[buf][kq * 4 + 0][n] = rb[i].x;
                Bs[buf][kq * 4 + 1][n] = rb[i].y;
                Bs[buf][kq * 4 + 2][n] = rb[i].z;
                Bs[buf][kq * 4 + 3][n] = rb[i].w;
            }
        }
    };

    float acc[TM][TN];
    #pragma unroll
    for (int i = 0; i < TM; i++)
        #pragma unroll
        for (int j = 0; j < TN; j++) acc[i][j] = 0.f;

    fetch(0); stage(0); __syncthreads();
    const int ntiles = Ktot / BK;
    for (int t = 0; t < ntiles; t++) {
        int cur = t & 1;
        if (t + 1 < ntiles) fetch(t + 1);
        #pragma unroll
        for (int kk = 0; kk < BK; kk++) {
            float a[TM], b[TN];
            #pragma unroll
            for (int i = 0; i < TM; i++) a[i] = As[cur][kk][ty * TM + i];
            #pragma unroll
            for (int j = 0; j < TN; j++) b[j] = Bs[cur][kk][tx * TN + j];
            #pragma unroll
            for (int i = 0; i < TM; i++)
                #pragma unroll
                for (int j = 0; j < TN; j++) acc[i][j] += a[i] * b[j];
        }
        if (t + 1 < ntiles) stage(cur ^ 1);
        __syncthreads();
    }

    #pragma unroll
    for (int i = 0; i < TM; i++) {
        int r = row0 + ty * TM + i;
        #pragma unroll
        for (int j = 0; j < TN; j++) {
            int c = col0 + tx * TN + j;
            float v = alpha * acc[i][j];
            if (biasg) v += biasg[c];
            Cg[(long)r * ldc + c] = v;
        }
    }
}

// ---------------- fused attention v3 ----------------
// Swizzled nb (stride 256, 64 KB), u via warp-uniform __ldg, combine folded
// into softmax. smem = 19080 floats = 76320 B -> 3 CTAs/SM.
#define ATTN_SMEM_BYTES ((16384 + 2048 + 512 + 64 + 8 + 64) * 4)
#define SWZ(row, c4) ((c4) ^ ((row) & 15))

__global__ __launch_bounds__(256) void attn_kernel(
        const float* __restrict__ nb,
        const unsigned int* __restrict__ e32,
        const float* __restrict__ ebt,
        const float* __restrict__ bk) {
    extern __shared__ float sm[];
    float4* nbs4  = (float4*)sm;             // 4096 float4 (64 rows x 64 slots)
    float*  part  = sm + 16384;              // 2048  [h*256 + q*64 + n]
    float*  attn_s= part + 2048;             // 512   [h*64 + n]
    float*  tbl   = attn_s + 512;            // 64    [h*8 + e]
    float*  kb_s  = tbl + 64;                // 8
    int*    et_s  = (int*)(kb_s + 8);        // 64

    const int b = blockIdx.x;
    const int t = threadIdx.x;

    // ---- stage nb (swizzled), et, tbl, kbias ----
    const float4* nbg = (const float4*)(nb + (long)b * NNB * DM);
    #pragma unroll
    for (int i = 0; i < 16; i++) {
        int f = t + i * 256;
        int row = f >> 6, c4 = f & 63;
        nbs4[row * 64 + SWZ(row, c4)] = nbg[f];
    }
    if (t < NNB) {
        int v = (d_or == 0u) ? (int)e32[(long)b * (2 * NNB) + 2 * t]
                             : (int)e32[(long)b * NNB + t];
        et_s[t] = v;
        tbl[t] = ebt[(t & 7) * NH + (t >> 3)];   // tbl[h*8+e] = ebt[e][h]
    }
    {
        const int w = t >> 5, l = t & 31;
        float s = d_Q[(long)b * DM + w * HD + l] * bk[w * HD + l];
        #pragma unroll
        for (int o = 16; o; o >>= 1) s += __shfl_xor_sync(0xffffffffu, s, o);
        if (l == 0) kb_s[w] = SCALE * s;
    }
    __syncthreads();

    // ---- phase 1: partial logits. thread = (n = t&63, quarter q = t>>6) ----
    {
        const int n = t & 63, q = t >> 6;
        const float4* ub = (const float4*)(d_U + (long)b * 2048 + q * 64);
        float acc[NH];
        #pragma unroll
        for (int h = 0; h < NH; h++) acc[h] = 0.f;
        #pragma unroll 4
        for (int c4 = 0; c4 < 16; c4++) {
            float4 x = nbs4[n * 64 + SWZ(n, q * 16 + c4)];
            #pragma unroll
            for (int h = 0; h < NH; h++) {
                float4 u = __ldg(ub + h * 64 + c4);   // warp-uniform
                acc[h] += u.x * x.x + u.y * x.y + u.z * x.z + u.w * x.w;
            }
        }
        #pragma unroll
        for (int h = 0; h < NH; h++) part[h * 256 + q * 64 + n] = acc[h];
    }
    __syncthreads();

    // ---- softmax with inline combine: warp w = head w ----
    {
        const int w = t >> 5, l = t & 31;
        float lg0 = kb_s[w] + tbl[w * 8 + et_s[l]];
        float lg1 = kb_s[w] + tbl[w * 8 + et_s[l + 32]];
        #pragma unroll
        for (int q = 0; q < 4; q++) {
            lg0 += part[w * 256 + q * 64 + l];
            lg1 += part[w * 256 + q * 64 + l + 32];
        }
        float m = fmaxf(lg0, lg1);
        #pragma unroll
        for (int o = 16; o; o >>= 1) m = fmaxf(m, __shfl_xor_sync(0xffffffffu, m, o));
        float e0 = __expf(lg0 - m), e1 = __expf(lg1 - m);
        float s = e0 + e1;
        #pragma unroll
        for (int o = 16; o; o >>= 1) s += __shfl_xor_sync(0xffffffffu, s, o);
        float inv = 1.f / s;
        attn_s[w * 64 + l]      = e0 * inv;
        attn_s[w * 64 + 32 + l] = e1 * inv;
    }
    __syncthreads();

    // ---- phase 2: ctx. thread = (c4 = t&63, head-pair hp = t>>6) ----
    {
        const int c4 = t & 63, hp = t >> 6;
        const float* a0p = attn_s + hp * 64;
        const float* a1p = attn_s + (hp + 4) * 64;
        float4 a0 = {0.f, 0.f, 0.f, 0.f};
        float4 a1 = {0.f, 0.f, 0.f, 0.f};
        #pragma unroll 8
        for (int n = 0; n < NNB; n++) {
            float4 x = nbs4[n * 64 + SWZ(n, c4)];
            float w0 = a0p[n], w1 = a1p[n];
            a0.x += w0 * x.x; a0.y += w0 * x.y; a0.z += w0 * x.z; a0.w += w0 * x.w;
            a1.x += w1 * x.x; a1.y += w1 * x.y; a1.z += w1 * x.z; a1.w += w1 * x.w;
        }
        float4* cg = (float4*)(d_ctx + (long)b * 2048);
        cg[hp * 64 + c4]       = a0;
        cg[(hp + 4) * 64 + c4] = a1;
    }
}

// ---------------- LayerNorm + ReLU (warp per row, float4) ----------------
__global__ void ln_relu_kernel(const float* __restrict__ g,
                               const float* __restrict__ be,
                               float* __restrict__ out) {
    const int b = blockIdx.x * 8 + (threadIdx.x >> 5);
    const int l = threadIdx.x & 31;
    const float4* yr = (const float4*)(d_y + (long)b * DM) + l * 2;
    float4 v0 = yr[0], v1 = yr[1];
    float s = v0.x + v0.y + v0.z + v0.w + v1.x + v1.y + v1.z + v1.w;
    #pragma unroll
    for (int o = 16; o; o >>= 1) s += __shfl_xor_sync(0xffffffffu, s, o);
    float mu = s * (1.f / 256.f);
    float vs = 0.f;
    {
        float d;
        d = v0.x - mu; vs += d * d;  d = v0.y - mu; vs += d * d;
        d = v0.z - mu; vs += d * d;  d = v0.w - mu; vs += d * d;
        d = v1.x - mu; vs += d * d;  d = v1.y - mu; vs += d * d;
        d = v1.z - mu; vs += d * d;  d = v1.w - mu; vs += d * d;
    }
    #pragma unroll
    for (int o = 16; o; o >>= 1) vs += __shfl_xor_sync(0xffffffffu, vs, o);
    float r = rsqrtf(vs * (1.f / 256.f) + 1e-5f);
    const float4* gp = (const float4*)g + l * 2;
    const float4* bp = (const float4*)be + l * 2;
    float4* op = (float4*)(out + (long)b * DM) + l * 2;
    float4 g0 = gp[0], g1 = gp[1], b0 = bp[0], b1 = bp[1];
    float4 o0, o1;
    o0.x = fmaxf((v0.x - mu) * r * g0.x + b0.x, 0.f);
    o0.y = fmaxf((v0.y - mu) * r * g0.y + b0.y, 0.f);
    o0.z = fmaxf((v0.z - mu) * r * g0.z + b0.z, 0.f);
    o0.w = fmaxf((v0.w - mu) * r * g0.w + b0.w, 0.f);
    o1.x = fmaxf((v1.x - mu) * r * g1.x + b1.x, 0.f);
    o1.y = fmaxf((v1.y - mu) * r * g1.y + b1.y, 0.f);
    o1.z = fmaxf((v1.z - mu) * r * g1.z + b1.z, 0.f);
    o1.w = fmaxf((v1.w - mu) * r * g1.w + b1.w, 0.f);
    op[0] = o0; op[1] = o1;
}

// ---------------- host launcher ----------------
extern "C" void kernel_launch(void* const* d_in, const int* in_sizes, int n_in,
                              void* d_out, int out_size) {
    const float* cde = (const float*)d_in[0];
    const float* nb  = (const float*)d_in[1];
    const unsigned int* et = (const unsigned int*)d_in[2];
    const float* Wq = (const float*)d_in[3];
    const float* bq = (const float*)d_in[4];
    const float* Wk = (const float*)d_in[5];
    const float* bk = (const float*)d_in[6];
    const float* Wv = (const float*)d_in[7];
    const float* bv = (const float*)d_in[8];
    const float* Wo = (const float*)d_in[9];
    const float* bo = (const float*)d_in[10];
    const float* ebt = (const float*)d_in[11];
    const float* Wf = (const float*)d_in[12];
    const float* bfv = (const float*)d_in[13];
    const float* lg = (const float*)d_in[14];
    const float* lb = (const float*)d_in[15];
    float* out = (float*)d_out;

    float *pQ, *pCtx, *pAtt, *pY, *pWoT, *pWc, *pB1;
    cudaGetSymbolAddress((void**)&pQ,   d_Q);
    cudaGetSymbolAddress((void**)&pCtx, d_ctx);
    cudaGetSymbolAddress((void**)&pAtt, d_att);
    cudaGetSymbolAddress((void**)&pY,   d_y);
    cudaGetSymbolAddress((void**)&pWoT, d_WoT);
    cudaGetSymbolAddress((void**)&pWc,  d_Wc);
    cudaGetSymbolAddress((void**)&pB1,  d_b1);

    cudaFuncSetAttribute(attn_kernel,
                         cudaFuncAttributeMaxDynamicSharedMemorySize,
                         ATTN_SMEM_BYTES);

    // 1) prep (transposes + b1 + edge detect)
    prep_kernel<<<256, 256>>>(Wk, Wo, Wf, bo, bfv, et);
    // 2) Q = cde @ Wq^T + bq
    gemm2_kernel<64, 64, 8, 4><<<dim3(DM / 64, BATCH / 64, 1), 128>>>(
        cde, DM, 0, Wq, DM, 0, nullptr, 0, nullptr, 0,
        bq, 0, pQ, DM, 0, DM, DM, 1.f);
    // 3) U (dedicated kernel, K=32 single pass)
    ugemm_kernel<<<dim3(2, BATCH / 128, NH), 256>>>();
    // 4) fused attention  (launch #4 -> ncu capture target)
    attn_kernel<<<BATCH, 256, ATTN_SMEM_BYTES>>>(nb, et, ebt, bk);
    // 5) Wc = Wf[:, :256] @ Wo
    gemm2_kernel<64, 64, 8, 4><<<dim3(DM / 64, DM / 64, 1), 128>>>(
        Wf, 2 * DM, 0, pWoT, DM, 0, nullptr, 0, nullptr, 0,
        nullptr, 0, pWc, DM, 0, DM, DM, 1.f);
    // 6) att[b, h*32+d] = Wv_h[d,:].ctx[b,h,:] + bv
    gemm2_kernel<128, 32, 8, 2><<<dim3(1, BATCH / 128, NH), 256>>>(
        pCtx, NH * DM, DM, Wv, DM, (long)HD * DM, nullptr, 0, nullptr, 0,
        bv, HD, pAtt, DM, HD, DM, DM, 1.f);
    // 7) y = att @ Wc^T + cde @ Wf[:,256:]^T + b1
    gemm2_kernel<64, 64, 8, 4><<<dim3(DM / 64, BATCH / 64, 1), 128>>>(
        pAtt, DM, 0, pWc, DM, 0, cde, DM, Wf + DM, 2 * DM,
        pB1, 0, pY, DM, 0, DM, 2 * DM, 1.f);
    // 8) LayerNorm + ReLU -> out
    ln_relu_kernel<<<BATCH / 8, 256>>>(lg, lb, out);
}

// round 7
// speedup vs baseline: 1.1449x; 1.1449x over previous
#include <cuda_runtime.h>
#include <cuda_bf16.h>
#include <math.h>

#define BATCH 4096
#define NNB   64
#define DM    256
#define NH    8
#define HD    32
#define SCALE 0.17677669529663687f   // 1/sqrt(32)
#define NBS   260                    // nb smem row stride (floats, float4-aligned)

// ---------------- scratch ----------------
__device__ float d_Q  [BATCH * DM];
__device__ float d_U  [BATCH * NH * DM];
__device__ float d_ctx[BATCH * NH * DM];
__device__ float d_att[BATCH * DM];
__device__ float d_y  [BATCH * DM];
__device__ float d_WkT[NH * DM * HD];      // [h][c][d]
__device__ float d_WoT[DM * DM];
__device__ float d_Wc [DM * DM];
__device__ float d_b1 [DM];
__device__ unsigned int d_or = 0u;         // OR of odd words; 0 => int64

// ---------------- prep: transposes + b1 + edge-dtype detect ----------------
__global__ void prep_kernel(const float* __restrict__ Wk,
                            const float* __restrict__ Wo,
                            const float* __restrict__ Wf,
                            const float* __restrict__ bo,
                            const float* __restrict__ bfv,
                            const unsigned int* __restrict__ e32) {
    const int blk = blockIdx.x, t = threadIdx.x;
    const int i = blk * 256 + t;                 // 0..65535
    { int dd = i & 31, c = (i >> 5) & 255, h = i >> 13;
      d_WkT[i] = Wk[(h * HD + dd) * DM + c]; }
    { int j = i >> 8, m = i & 255;
      d_WoT[i] = Wo[m * DM + j]; }
    if (blk < 32) {
        int o = blk * 8 + (t >> 5), l = t & 31;
        float s = 0.f;
        #pragma unroll
        for (int m = l; m < DM; m += 32) s += Wf[o * 2 * DM + m] * bo[m];
        #pragma unroll
        for (int off = 16; off; off >>= 1) s += __shfl_xor_sync(0xffffffffu, s, off);
        if (l == 0) d_b1[o] = bfv[o] + s;
    }
    unsigned int acc = 0u;
    #pragma unroll
    for (int w = i; w < BATCH * NNB; w += 65536) acc |= e32[2 * w + 1];
    #pragma unroll
    for (int o = 16; o; o >>= 1) acc |= __shfl_xor_sync(0xffffffffu, acc, o);
    __shared__ unsigned int sOr;
    if (t == 0) sOr = 0u;
    __syncthreads();
    if ((t & 31) == 0 && acc) atomicOr(&sOr, acc);
    __syncthreads();
    if (t == 0 && sOr) atomicOr(&d_or, sOr);
}

// ---------------- double-buffered NT GEMM with optional dual K-source -------
template<int BM, int BN, int TM, int TN>
__global__ void gemm2_kernel(const float* __restrict__ A1, int lda1, long az1,
                             const float* __restrict__ B1, int ldb1, long bz1,
                             const float* __restrict__ A2, int lda2,
                             const float* __restrict__ B2, int ldb2,
                             const float* __restrict__ bias, long biasz,
                             float* __restrict__ C, int ldc, long cz,
                             int K1, int Ktot, float alpha) {
    constexpr int BK = 16;
    constexpr int NT = (BM / TM) * (BN / TN);
    constexpr int PAD = 4;
    constexpr int A4 = BM * BK / 4;
    constexpr int B4 = BN * BK / 4;
    constexpr int NA = (A4 + NT - 1) / NT;
    constexpr int NB = (B4 + NT - 1) / NT;

    __shared__ float As[2][BK][BM + PAD];
    __shared__ float Bs[2][BK][BN + PAD];

    const int tid = threadIdx.x;
    const int tx = tid % (BN / TN);
    const int ty = tid / (BN / TN);
    const int row0 = blockIdx.y * BM;
    const int col0 = blockIdx.x * BN;
    const int z = blockIdx.z;

    const float* A1g = A1 + (long)z * az1;
    const float* B1g = B1 + (long)z * bz1;
    float* Cg = C + (long)z * cz;
    const float* biasg = bias ? bias + (long)z * biasz : nullptr;

    float4 ra[NA], rb[NB];

    auto fetch = [&](int t) {
        int k0 = t * BK;
        const float *Ap, *Bp; int lda, ldb, k;
        if (k0 < K1) { Ap = A1g; lda = lda1; Bp = B1g; ldb = ldb1; k = k0; }
        else         { Ap = A2;  lda = lda2; Bp = B2;  ldb = ldb2; k = k0 - K1; }
        #pragma unroll
        for (int i = 0; i < NA; i++) {
            int f = tid + i * NT;
            if (f < A4) {
                int r = f >> 2, kq = f & 3;
                ra[i] = *reinterpret_cast<const float4*>(Ap + (long)(row0 + r) * lda + k + kq * 4);
            }
        }
        #pragma unroll
        for (int i = 0; i < NB; i++) {
            int f = tid + i * NT;
            if (f < B4) {
                int n = f >> 2, kq = f & 3;
                rb[i] = *reinterpret_cast<const float4*>(Bp + (long)(col0 + n) * ldb + k + kq * 4);
            }
        }
    };
    auto stage = [&](int buf) {
        #pragma unroll
        for (int i = 0; i < NA; i++) {
            int f = tid + i * NT;
            if (f < A4) {
                int r = f >> 2, kq = f & 3;
                As[buf][kq * 4 + 0][r] = ra[i].x;
                As[buf][kq * 4 + 1][r] = ra[i].y;
                As[buf][kq * 4 + 2][r] = ra[i].z;
                As[buf][kq * 4 + 3][r] = ra[i].w;
            }
        }
        #pragma unroll
        for (int i = 0; i < NB; i++) {
            int f = tid + i * NT;
            if (f < B4) {
                int n = f >> 2, kq = f & 3;
                Bs[buf][kq * 4 + 0][n] = rb[i].x;
                Bs[buf][kq * 4 + 1][n] = rb[i].y;
                Bs[buf][kq * 4 + 2][n] = rb[i].z;
                Bs[buf][kq * 4 + 3][n] = rb[i].w;
            }
        }
    };

    float acc[TM][TN];
    #pragma unroll
    for (int i = 0; i < TM; i++)
        #pragma unroll
        for (int j = 0; j < TN; j++) acc[i][j] = 0.f;

    fetch(0); stage(0); __syncthreads();
    const int ntiles = Ktot / BK;
    for (int t = 0; t < ntiles; t++) {
        int cur = t & 1;
        if (t + 1 < ntiles) fetch(t + 1);
        #pragma unroll
        for (int kk = 0; kk < BK; kk++) {
            float a[TM], b[TN];
            #pragma unroll
            for (int i = 0; i < TM; i++) a[i] = As[cur][kk][ty * TM + i];
            #pragma unroll
            for (int j = 0; j < TN; j++) b[j] = Bs[cur][kk][tx * TN + j];
            #pragma unroll
            for (int i = 0; i < TM; i++)
                #pragma unroll
                for (int j = 0; j < TN; j++) acc[i][j] += a[i] * b[j];
        }
        if (t + 1 < ntiles) stage(cur ^ 1);
        __syncthreads();
    }

    #pragma unroll
    for (int i = 0; i < TM; i++) {
        int r = row0 + ty * TM + i;
        #pragma unroll
        for (int j = 0; j < TN; j++) {
            int c = col0 + tx * TN + j;
            float v = alpha * acc[i][j];
            if (biasg) v += biasg[c];
            Cg[(long)r * ldc + c] = v;
        }
    }
}

// ---------------- fused attention v4 ----------------
// smem layout (floats):
//   nb_s   [0, 16640)       64 rows x stride 260
//   attn_t [16640, 17152)   [n*8 + h]
//   tbl    [17152, 17216)   [e*8 + h] (= ebt layout)
//   kb_s   [17216, 17224)
//   et_s   [17224, 17288)   (ints)
//   u_s    [17288, 19336)
//   part   [19336, 21384)   [h*256 + q*64 + n]
//   part2  = float4 array at 17288, 2048 float4 = [17288, 25480)
//            (aliases u_s + part + 16KB beyond; both dead by phase 2)
#define ATTN_SMEM_BYTES (25480 * 4)

__global__ __launch_bounds__(256) void attn_kernel(
        const float* __restrict__ nb,
        const unsigned int* __restrict__ e32,
        const float* __restrict__ ebt,
        const float* __restrict__ bk) {
    extern __shared__ float sm[];
    float*  nb_s   = sm;
    float*  attn_t = sm + 16640;
    float*  tbl    = sm + 17152;
    float*  kb_s   = sm + 17216;
    int*    et_s   = (int*)(sm + 17224);
    float*  u_s    = sm + 17288;
    float*  part   = sm + 19336;
    float4* part2  = (float4*)(sm + 17288);

    const int b = blockIdx.x;
    const int t = threadIdx.x;

    // ---- stage nb (padded stride), u, et, tbl, kbias ----
    const float4* nbg = (const float4*)(nb + (long)b * NNB * DM);
    #pragma unroll
    for (int i = 0; i < 16; i++) {
        int f = t + i * 256;
        int row = f >> 6, c4 = f & 63;
        *reinterpret_cast<float4*>(nb_s + row * NBS + c4 * 4) = nbg[f];
    }
    const float4* ug = (const float4*)(d_U + (long)b * 2048);
    *reinterpret_cast<float4*>(u_s + t * 4)        = ug[t];
    *reinterpret_cast<float4*>(u_s + 1024 + t * 4) = ug[256 + t];
    if (t < NNB) {
        int v = (d_or == 0u) ? (int)e32[(long)b * (2 * NNB) + 2 * t]
                             : (int)e32[(long)b * NNB + t];
        et_s[t] = v;
        tbl[t] = ebt[t];                 // tbl[e*8+h]
    }
    {
        const int w = t >> 5, l = t & 31;
        float s = d_Q[(long)b * DM + w * HD + l] * bk[w * HD + l];
        #pragma unroll
        for (int o = 16; o; o >>= 1) s += __shfl_xor_sync(0xffffffffu, s, o);
        if (l == 0) kb_s[w] = SCALE * s;
    }
    __syncthreads();

    // ---- phase 1: partial logits. thread = (n = t&63, quarter q = t>>6) ----
    {
        const int n = t & 63, q = t >> 6;
        const float* xr = nb_s + n * NBS + q * 64;
        const float* ur = u_s + q * 64;
        float acc[NH];
        #pragma unroll
        for (int h = 0; h < NH; h++) acc[h] = 0.f;
        #pragma unroll 4
        for (int c = 0; c < 64; c += 4) {
            float4 x = *reinterpret_cast<const float4*>(xr + c);
            #pragma unroll
            for (int h = 0; h < NH; h++) {
                float4 u = *reinterpret_cast<const float4*>(ur + h * DM + c);
                acc[h] += u.x * x.x + u.y * x.y + u.z * x.z + u.w * x.w;
            }
        }
        #pragma unroll
        for (int h = 0; h < NH; h++) part[h * 256 + q * 64 + n] = acc[h];
    }
    __syncthreads();

    // ---- softmax with inline combine: warp w = head w; writes attn_t[n][h] ----
    {
        const int w = t >> 5, l = t & 31;
        float lg0 = kb_s[w] + tbl[et_s[l] * NH + w];
        float lg1 = kb_s[w] + tbl[et_s[l + 32] * NH + w];
        #pragma unroll
        for (int q = 0; q < 4; q++) {
            lg0 += part[w * 256 + q * 64 + l];
            lg1 += part[w * 256 + q * 64 + l + 32];
        }
        float m = fmaxf(lg0, lg1);
        #pragma unroll
        for (int o = 16; o; o >>= 1) m = fmaxf(m, __shfl_xor_sync(0xffffffffu, m, o));
        float e0 = __expf(lg0 - m), e1 = __expf(lg1 - m);
        float s = e0 + e1;
        #pragma unroll
        for (int o = 16; o; o >>= 1) s += __shfl_xor_sync(0xffffffffu, s, o);
        float inv = 1.f / s;
        attn_t[l * 8 + w]        = e0 * inv;
        attn_t[(l + 32) * 8 + w] = e1 * inv;
    }
    __syncthreads();

    // ---- phase 2: thread (c4 = t&63, q = t>>6) owns rows {q+4j}, all 8 heads ----
    {
        const int c4 = t & 63, q = t >> 6;
        const float4* at4 = (const float4*)attn_t;
        float4 p0 = {0,0,0,0}, p1 = {0,0,0,0}, p2 = {0,0,0,0}, p3 = {0,0,0,0};
        float4 p4 = {0,0,0,0}, p5 = {0,0,0,0}, p6 = {0,0,0,0}, p7 = {0,0,0,0};
        #pragma unroll
        for (int j = 0; j < 16; j++) {
            int n = q + 4 * j;
            float4 x  = *reinterpret_cast<const float4*>(nb_s + n * NBS + c4 * 4);
            float4 a0 = at4[n * 2 + 0];   // heads 0-3 (warp-uniform broadcast)
            float4 a1 = at4[n * 2 + 1];   // heads 4-7
            p0.x += a0.x * x.x; p0.y += a0.x * x.y; p0.z += a0.x * x.z; p0.w += a0.x * x.w;
            p1.x += a0.y * x.x; p1.y += a0.y * x.y; p1.z += a0.y * x.z; p1.w += a0.y * x.w;
            p2.x += a0.z * x.x; p2.y += a0.z * x.y; p2.z += a0.z * x.z; p2.w += a0.z * x.w;
            p3.x += a0.w * x.x; p3.y += a0.w * x.y; p3.z += a0.w * x.z; p3.w += a0.w * x.w;
            p4.x += a1.x * x.x; p4.y += a1.x * x.y; p4.z += a1.x * x.z; p4.w += a1.x * x.w;
            p5.x += a1.y * x.x; p5.y += a1.y * x.y; p5.z += a1.y * x.z; p5.w += a1.y * x.w;
            p6.x += a1.z * x.x; p6.y += a1.z * x.y; p6.z += a1.z * x.z; p6.w += a1.z * x.w;
            p7.x += a1.w * x.x; p7.y += a1.w * x.y; p7.z += a1.w * x.z; p7.w += a1.w * x.w;
        }
        __syncthreads();   // part/u_s dead; part2 aliases them
        part2[0 * 256 + q * 64 + c4] = p0;
        part2[1 * 256 + q * 64 + c4] = p1;
        part2[2 * 256 + q * 64 + c4] = p2;
        part2[3 * 256 + q * 64 + c4] = p3;
        part2[4 * 256 + q * 64 + c4] = p4;
        part2[5 * 256 + q * 64 + c4] = p5;
        part2[6 * 256 + q * 64 + c4] = p6;
        part2[7 * 256 + q * 64 + c4] = p7;
    }
    __syncthreads();

    // ---- reduce partials over q, write ctx ----
    {
        float4* cg = (float4*)(d_ctx + (long)b * 2048);
        #pragma unroll
        for (int k = 0; k < 2; k++) {
            int o = t + k * 256;            // 0..511 = h*64 + c4
            int h = o >> 6, c4o = o & 63;
            float4 r0 = part2[h * 256 + 0 * 64 + c4o];
            float4 r1 = part2[h * 256 + 1 * 64 + c4o];
            float4 r2 = part2[h * 256 + 2 * 64 + c4o];
            float4 r3 = part2[h * 256 + 3 * 64 + c4o];
            float4 r;
            r.x = (r0.x + r1.x) + (r2.x + r3.x);
            r.y = (r0.y + r1.y) + (r2.y + r3.y);
            r.z = (r0.z + r1.z) + (r2.z + r3.z);
            r.w = (r0.w + r1.w) + (r2.w + r3.w);
            cg[o] = r;
        }
    }
}

// ---------------- LayerNorm + ReLU (warp per row, float4) ----------------
__global__ void ln_relu_kernel(const float* __restrict__ g,
                               const float* __restrict__ be,
                               float* __restrict__ out) {
    const int b = blockIdx.x * 8 + (threadIdx.x >> 5);
    const int l = threadIdx.x & 31;
    const float4* yr = (const float4*)(d_y + (long)b * DM) + l * 2;
    float4 v0 = yr[0], v1 = yr[1];
    float s = v0.x + v0.y + v0.z + v0.w + v1.x + v1.y + v1.z + v1.w;
    #pragma unroll
    for (int o = 16; o; o >>= 1) s += __shfl_xor_sync(0xffffffffu, s, o);
    float mu = s * (1.f / 256.f);
    float vs = 0.f;
    {
        float d;
        d = v0.x - mu; vs += d * d;  d = v0.y - mu; vs += d * d;
        d = v0.z - mu; vs += d * d;  d = v0.w - mu; vs += d * d;
        d = v1.x - mu; vs += d * d;  d = v1.y - mu; vs += d * d;
        d = v1.z - mu; vs += d * d;  d = v1.w - mu; vs += d * d;
    }
    #pragma unroll
    for (int o = 16; o; o >>= 1) vs += __shfl_xor_sync(0xffffffffu, vs, o);
    float r = rsqrtf(vs * (1.f / 256.f) + 1e-5f);
    const float4* gp = (const float4*)g + l * 2;
    const float4* bp = (const float4*)be + l * 2;
    float4* op = (float4*)(out + (long)b * DM) + l * 2;
    float4 g0 = gp[0], g1 = gp[1], b0 = bp[0], b1 = bp[1];
    float4 o0, o1;
    o0.x = fmaxf((v0.x - mu) * r * g0.x + b0.x, 0.f);
    o0.y = fmaxf((v0.y - mu) * r * g0.y + b0.y, 0.f);
    o0.z = fmaxf((v0.z - mu) * r * g0.z + b0.z, 0.f);
    o0.w = fmaxf((v0.w - mu) * r * g0.w + b0.w, 0.f);
    o1.x = fmaxf((v1.x - mu) * r * g1.x + b1.x, 0.f);
    o1.y = fmaxf((v1.y - mu) * r * g1.y + b1.y, 0.f);
    o1.z = fmaxf((v1.z - mu) * r * g1.z + b1.z, 0.f);
    o1.w = fmaxf((v1.w - mu) * r * g1.w + b1.w, 0.f);
    op[0] = o0; op[1] = o1;
}

// ---------------- host launcher ----------------
extern "C" void kernel_launch(void* const* d_in, const int* in_sizes, int n_in,
                              void* d_out, int out_size) {
    const float* cde = (const float*)d_in[0];
    const float* nb  = (const float*)d_in[1];
    const unsigned int* et = (const unsigned int*)d_in[2];
    const float* Wq = (const float*)d_in[3];
    const float* bq = (const float*)d_in[4];
    const float* Wk = (const float*)d_in[5];
    const float* bk = (const float*)d_in[6];
    const float* Wv = (const float*)d_in[7];
    const float* bv = (const float*)d_in[8];
    const float* Wo = (const float*)d_in[9];
    const float* bo = (const float*)d_in[10];
    const float* ebt = (const float*)d_in[11];
    const float* Wf = (const float*)d_in[12];
    const float* bfv = (const float*)d_in[13];
    const float* lg = (const float*)d_in[14];
    const float* lb = (const float*)d_in[15];
    float* out = (float*)d_out;

    float *pQ, *pU, *pCtx, *pAtt, *pY, *pWkT, *pWoT, *pWc, *pB1;
    cudaGetSymbolAddress((void**)&pQ,   d_Q);
    cudaGetSymbolAddress((void**)&pU,   d_U);
    cudaGetSymbolAddress((void**)&pCtx, d_ctx);
    cudaGetSymbolAddress((void**)&pAtt, d_att);
    cudaGetSymbolAddress((void**)&pY,   d_y);
    cudaGetSymbolAddress((void**)&pWkT, d_WkT);
    cudaGetSymbolAddress((void**)&pWoT, d_WoT);
    cudaGetSymbolAddress((void**)&pWc,  d_Wc);
    cudaGetSymbolAddress((void**)&pB1,  d_b1);

    cudaFuncSetAttribute(attn_kernel,
                         cudaFuncAttributeMaxDynamicSharedMemorySize,
                         ATTN_SMEM_BYTES);

    // 1) prep (transposes + b1 + edge detect)
    prep_kernel<<<256, 256>>>(Wk, Wo, Wf, bo, bfv, et);
    // 2) Q = cde @ Wq^T + bq
    gemm2_kernel<64, 64, 8, 4><<<dim3(DM / 64, BATCH / 64, 1), 128>>>(
        cde, DM, 0, Wq, DM, 0, nullptr, 0, nullptr, 0,
        bq, 0, pQ, DM, 0, DM, DM, 1.f);
    // 3) U[b,h,:] = SCALE * Qh^T Wk_h  (gemm2, proven)
    gemm2_kernel<64, 64, 8, 4><<<dim3(DM / 64, BATCH / 64, NH), 128>>>(
        pQ, DM, HD, pWkT, HD, (long)DM * HD, nullptr, 0, nullptr, 0,
        nullptr, 0, pU, NH * DM, DM, HD, HD, SCALE);
    // 4) fused attention  (launch #4 -> ncu capture target)
    attn_kernel<<<BATCH, 256, ATTN_SMEM_BYTES>>>(nb, et, ebt, bk);
    // 5) Wc = Wf[:, :256] @ Wo
    gemm2_kernel<64, 64, 8, 4><<<dim3(DM / 64, DM / 64, 1), 128>>>(
        Wf, 2 * DM, 0, pWoT, DM, 0, nullptr, 0, nullptr, 0,
        nullptr, 0, pWc, DM, 0, DM, DM, 1.f);
    // 6) att[b, h*32+d] = Wv_h[d,:].ctx[b,h,:] + bv
    gemm2_kernel<128, 32, 8, 2><<<dim3(1, BATCH / 128, NH), 256>>>(
        pCtx, NH * DM, DM, Wv, DM, (long)HD * DM, nullptr, 0, nullptr, 0,
        bv, HD, pAtt, DM, HD, DM, DM, 1.f);
    // 7) y = att @ Wc^T + cde @ Wf[:,256:]^T + b1
    gemm2_kernel<64, 64, 8, 4><<<dim3(DM / 64, BATCH / 64, 1), 128>>>(
        pAtt, DM, 0, pWc, DM, 0, cde, DM, Wf + DM, 2 * DM,
        pB1, 0, pY, DM, 0, DM, 2 * DM, 1.f);
    // 8) LayerNorm + ReLU -> out
    ln_relu_kernel<<<BATCH / 8, 256>>>(lg, lb, out);
}

// round 8
// speedup vs baseline: 1.1631x; 1.0159x over previous
#include <cuda_runtime.h>
#include <cuda_bf16.h>
#include <math.h>

#define BATCH 4096
#define NNB   64
#define DM    256
#define NH    8
#define HD    32
#define SCALE 0.17677669529663687f   // 1/sqrt(32)

// ---------------- f32x2 packed helpers ----------------
__device__ __forceinline__ unsigned long long pk2(float x, float y) {
    unsigned long long r;
    asm("mov.b64 %0, {%1, %2};" : "=l"(r) : "f"(x), "f"(y));
    return r;
}
__device__ __forceinline__ void fma2(unsigned long long& d,
                                     unsigned long long a,
                                     unsigned long long b) {
    asm("fma.rn.f32x2 %0, %1, %2, %0;" : "+l"(d) : "l"(a), "l"(b));
}
__device__ __forceinline__ float2 upk(unsigned long long v) {
    float2 r;
    asm("mov.b64 {%0, %1}, %2;" : "=f"(r.x), "=f"(r.y) : "l"(v));
    return r;
}

// ---------------- scratch ----------------
__device__ float d_Q  [BATCH * DM];
__device__ float d_U  [BATCH * NH * DM];
__device__ float d_ctx[BATCH * NH * DM];
__device__ float d_att[BATCH * DM];
__device__ float d_y  [BATCH * DM];
__device__ float d_WkT[NH * DM * HD];      // [h][c][d]
__device__ float d_WoT[DM * DM];
__device__ float d_Wc [DM * DM];
__device__ float d_b1 [DM];
__device__ unsigned int d_or = 0u;         // OR of odd words; 0 => int64

// ---------------- prep: transposes + b1 + edge-dtype detect ----------------
__global__ void prep_kernel(const float* __restrict__ Wk,
                            const float* __restrict__ Wo,
                            const float* __restrict__ Wf,
                            const float* __restrict__ bo,
                            const float* __restrict__ bfv,
                            const unsigned int* __restrict__ e32) {
    const int blk = blockIdx.x, t = threadIdx.x;
    const int i = blk * 256 + t;                 // 0..65535
    { int dd = i & 31, c = (i >> 5) & 255, h = i >> 13;
      d_WkT[i] = Wk[(h * HD + dd) * DM + c]; }
    { int j = i >> 8, m = i & 255;
      d_WoT[i] = Wo[m * DM + j]; }
    if (blk < 32) {
        int o = blk * 8 + (t >> 5), l = t & 31;
        float s = 0.f;
        #pragma unroll
        for (int m = l; m < DM; m += 32) s += Wf[o * 2 * DM + m] * bo[m];
        #pragma unroll
        for (int off = 16; off; off >>= 1) s += __shfl_xor_sync(0xffffffffu, s, off);
        if (l == 0) d_b1[o] = bfv[o] + s;
    }
    unsigned int acc = 0u;
    #pragma unroll
    for (int w = i; w < BATCH * NNB; w += 65536) acc |= e32[2 * w + 1];
    #pragma unroll
    for (int o = 16; o; o >>= 1) acc |= __shfl_xor_sync(0xffffffffu, acc, o);
    __shared__ unsigned int sOr;
    if (t == 0) sOr = 0u;
    __syncthreads();
    if ((t & 31) == 0 && acc) atomicOr(&sOr, acc);
    __syncthreads();
    if (t == 0 && sOr) atomicOr(&d_or, sOr);
}

// ---------------- double-buffered NT GEMM (FFMA2 inner), dual K-source ------
template<int BM, int BN, int TM, int TN>
__global__ void gemm2_kernel(const float* __restrict__ A1, int lda1, long az1,
                             const float* __restrict__ B1, int ldb1, long bz1,
                             const float* __restrict__ A2, int lda2,
                             const float* __restrict__ B2, int ldb2,
                             const float* __restrict__ bias, long biasz,
                             float* __restrict__ C, int ldc, long cz,
                             int K1, int Ktot, float alpha) {
    static_assert(TN % 2 == 0, "TN must be even");
    constexpr int BK = 16;
    constexpr int NT = (BM / TM) * (BN / TN);
    constexpr int PAD = 4;
    constexpr int TN2 = TN / 2;
    constexpr int A4 = BM * BK / 4;
    constexpr int B4 = BN * BK / 4;
    constexpr int NA = (A4 + NT - 1) / NT;
    constexpr int NB = (B4 + NT - 1) / NT;

    __shared__ __align__(16) float As[2][BK][BM + PAD];
    __shared__ __align__(16) float Bs[2][BK][BN + PAD];

    const int tid = threadIdx.x;
    const int tx = tid % (BN / TN);
    const int ty = tid / (BN / TN);
    const int row0 = blockIdx.y * BM;
    const int col0 = blockIdx.x * BN;
    const int z = blockIdx.z;

    const float* A1g = A1 + (long)z * az1;
    const float* B1g = B1 + (long)z * bz1;
    float* Cg = C + (long)z * cz;
    const float* biasg = bias ? bias + (long)z * biasz : nullptr;

    float4 ra[NA], rb[NB];

    auto fetch = [&](int t) {
        int k0 = t * BK;
        const float *Ap, *Bp; int lda, ldb, k;
        if (k0 < K1) { Ap = A1g; lda = lda1; Bp = B1g; ldb = ldb1; k = k0; }
        else         { Ap = A2;  lda = lda2; Bp = B2;  ldb = ldb2; k = k0 - K1; }
        #pragma unroll
        for (int i = 0; i < NA; i++) {
            int f = tid + i * NT;
            if (f < A4) {
                int r = f >> 2, kq = f & 3;
                ra[i] = *reinterpret_cast<const float4*>(Ap + (long)(row0 + r) * lda + k + kq * 4);
            }
        }
        #pragma unroll
        for (int i = 0; i < NB; i++) {
            int f = tid + i * NT;
            if (f < B4) {
                int n = f >> 2, kq = f & 3;
                rb[i] = *reinterpret_cast<const float4*>(Bp + (long)(col0 + n) * ldb + k + kq * 4);
            }
        }
    };
    auto stage = [&](int buf) {
        #pragma unroll
        for (int i = 0; i < NA; i++) {
            int f = tid + i * NT;
            if (f < A4) {
                int r = f >> 2, kq = f & 3;
                As[buf][kq * 4 + 0][r] = ra[i].x;
                As[buf][kq * 4 + 1][r] = ra[i].y;
                As[buf][kq * 4 + 2][r] = ra[i].z;
                As[buf][kq * 4 + 3][r] = ra[i].w;
            }
        }
        #pragma unroll
        for (int i = 0; i < NB; i++) {
            int f = tid + i * NT;
            if (f < B4) {
                int n = f >> 2, kq = f & 3;
                Bs[buf][kq * 4 + 0][n] = rb[i].x;
                Bs[buf][kq * 4 + 1][n] = rb[i].y;
                Bs[buf][kq * 4 + 2][n] = rb[i].z;
                Bs[buf][kq * 4 + 3][n] = rb[i].w;
            }
        }
    };

    unsigned long long acc2[TM][TN2];
    #pragma unroll
    for (int i = 0; i < TM; i++)
        #pragma unroll
        for (int j = 0; j < TN2; j++) acc2[i][j] = 0ull;

    fetch(0); stage(0); __syncthreads();
    const int ntiles = Ktot / BK;
    for (int t = 0; t < ntiles; t++) {
        int cur = t & 1;
        if (t + 1 < ntiles) fetch(t + 1);
        #pragma unroll
        for (int kk = 0; kk < BK; kk++) {
            float a[TM];
            #pragma unroll
            for (int i = 0; i < TM; i++) a[i] = As[cur][kk][ty * TM + i];
            unsigned long long bp[TN2];
            const unsigned long long* bq =
                reinterpret_cast<const unsigned long long*>(&Bs[cur][kk][tx * TN]);
            #pragma unroll
            for (int j = 0; j < TN2; j++) bp[j] = bq[j];
            #pragma unroll
            for (int i = 0; i < TM; i++) {
                unsigned long long ad = pk2(a[i], a[i]);
                #pragma unroll
                for (int j = 0; j < TN2; j++) fma2(acc2[i][j], ad, bp[j]);
            }
        }
        if (t + 1 < ntiles) stage(cur ^ 1);
        __syncthreads();
    }

    #pragma unroll
    for (int i = 0; i < TM; i++) {
        int r = row0 + ty * TM + i;
        #pragma unroll
        for (int j = 0; j < TN2; j++) {
            float2 v = upk(acc2[i][j]);
            int c = col0 + tx * TN + j * 2;
            float v0 = alpha * v.x, v1 = alpha * v.y;
            if (biasg) { v0 += biasg[c]; v1 += biasg[c + 1]; }
            Cg[(long)r * ldc + c]     = v0;
            Cg[(long)r * ldc + c + 1] = v1;
        }
    }
}

// ---------------- fused attention v5 (FFMA2 + transposed tile) ---------------
// smem floats:
//   nb_t  [0, 16640)      transposed: slot c4 (0..63) x 65 float4 (n + pad)
//   u_s   [16640, 18688)  2048 fp32
//   part  [18688, 20736)  [h*256 + q*64 + n]
//   adup  [20736, 21760)  [n*16 + h*2 + {0,1}] duplicated attn pairs
//   tbl   [21760, 21824)  [e*8 + h]
//   kb_s  [21824, 21832)
//   et_s  [21832, 21896)  ints
//   part2 (phase 2 only) aliases [0, 8192) floats over dead nb_t
#define U_S_OFF   16640
#define PART_OFF  18688
#define ADUP_OFF  20736
#define TBL_OFF   21760
#define KB_OFF    21824
#define ET_OFF    21832
#define ATTN_SMEM_BYTES (21896 * 4)

__global__ __launch_bounds__(256) void attn_kernel(
        const float* __restrict__ nb,
        const unsigned int* __restrict__ e32,
        const float* __restrict__ ebt,
        const float* __restrict__ bk) {
    extern __shared__ __align__(16) float sm[];
    float4* nbt  = (float4*)sm;
    float*  u_s  = sm + U_S_OFF;
    float*  part = sm + PART_OFF;
    float*  adup = sm + ADUP_OFF;
    float*  tbl  = sm + TBL_OFF;
    float*  kb_s = sm + KB_OFF;
    int*    et_s = (int*)(sm + ET_OFF);

    const int b = blockIdx.x;
    const int t = threadIdx.x;

    // ---- stage nb transposed, u, et, tbl, kbias ----
    const float4* nbg = (const float4*)(nb + (long)b * NNB * DM);
    #pragma unroll
    for (int i = 0; i < 16; i++) {
        int f = t + i * 256;
        int row = f >> 6, c4 = f & 63;
        nbt[c4 * 65 + row] = nbg[f];
    }
    const float4* ug = (const float4*)(d_U + (long)b * 2048);
    *reinterpret_cast<float4*>(u_s + t * 4)        = ug[t];
    *reinterpret_cast<float4*>(u_s + 1024 + t * 4) = ug[256 + t];
    if (t < NNB) {
        int v = (d_or == 0u) ? (int)e32[(long)b * (2 * NNB) + 2 * t]
                             : (int)e32[(long)b * NNB + t];
        et_s[t] = v;
        tbl[t] = ebt[t];                 // [e*8+h]
    }
    {
        const int w = t >> 5, l = t & 31;
        float s = d_Q[(long)b * DM + w * HD + l] * bk[w * HD + l];
        #pragma unroll
        for (int o = 16; o; o >>= 1) s += __shfl_xor_sync(0xffffffffu, s, o);
        if (l == 0) kb_s[w] = SCALE * s;
    }
    __syncthreads();

    // ---- phase 1: partial logits. thread = (n = t&63, q = t>>6), FFMA2 ----
    {
        const int n = t & 63, q = t >> 6;
        unsigned long long acc2[NH];
        #pragma unroll
        for (int h = 0; h < NH; h++) acc2[h] = 0ull;
        #pragma unroll
        for (int c2 = 0; c2 < 8; c2++) {             // 8 floats per chunk
            int s0 = q * 16 + c2 * 2;
            ulonglong2 x01 = *reinterpret_cast<const ulonglong2*>(nbt + s0 * 65 + n);
            ulonglong2 x23 = *reinterpret_cast<const ulonglong2*>(nbt + (s0 + 1) * 65 + n);
            #pragma unroll
            for (int h = 0; h < NH; h++) {
                const ulonglong2* up =
                    reinterpret_cast<const ulonglong2*>(u_s + h * DM + q * 64 + c2 * 8);
                ulonglong2 ua = up[0], ub = up[1];
                fma2(acc2[h], ua.x, x01.x);
                fma2(acc2[h], ua.y, x01.y);
                fma2(acc2[h], ub.x, x23.x);
                fma2(acc2[h], ub.y, x23.y);
            }
        }
        #pragma unroll
        for (int h = 0; h < NH; h++) {
            float2 v = upk(acc2[h]);
            part[h * 256 + q * 64 + n] = v.x + v.y;
        }
    }
    __syncthreads();

    // ---- softmax with inline combine: warp w = head w; writes adup pairs ----
    {
        const int w = t >> 5, l = t & 31;
        float lg0 = kb_s[w] + tbl[et_s[l] * NH + w];
        float lg1 = kb_s[w] + tbl[et_s[l + 32] * NH + w];
        #pragma unroll
        for (int q = 0; q < 4; q++) {
            lg0 += part[w * 256 + q * 64 + l];
            lg1 += part[w * 256 + q * 64 + l + 32];
        }
        float m = fmaxf(lg0, lg1);
        #pragma unroll
        for (int o = 16; o; o >>= 1) m = fmaxf(m, __shfl_xor_sync(0xffffffffu, m, o));
        float e0 = __expf(lg0 - m), e1 = __expf(lg1 - m);
        float s = e0 + e1;
        #pragma unroll
        for (int o = 16; o; o >>= 1) s += __shfl_xor_sync(0xffffffffu, s, o);
        float inv = 1.f / s;
        float a0 = e0 * inv, a1 = e1 * inv;
        adup[l * 16 + w * 2]            = a0;
        adup[l * 16 + w * 2 + 1]        = a0;
        adup[(l + 32) * 16 + w * 2]     = a1;
        adup[(l + 32) * 16 + w * 2 + 1] = a1;
    }
    __syncthreads();

    // ---- phase 2: thread (c4 = t&63, q = t>>6) rows {q+4j}, all 8 heads ----
    {
        const int c4 = t & 63, q = t >> 6;
        unsigned long long acc[NH][2];
        #pragma unroll
        for (int h = 0; h < NH; h++) { acc[h][0] = 0ull; acc[h][1] = 0ull; }
        #pragma unroll
        for (int j = 0; j < 16; j++) {
            int n = q + 4 * j;
            ulonglong2 x = *reinterpret_cast<const ulonglong2*>(nbt + c4 * 65 + n);
            const ulonglong2* ap = reinterpret_cast<const ulonglong2*>(adup + n * 16);
            ulonglong2 a01 = ap[0], a23 = ap[1], a45 = ap[2], a67 = ap[3];
            fma2(acc[0][0], a01.x, x.x); fma2(acc[0][1], a01.x, x.y);
            fma2(acc[1][0], a01.y, x.x); fma2(acc[1][1], a01.y, x.y);
            fma2(acc[2][0], a23.x, x.x); fma2(acc[2][1], a23.x, x.y);
            fma2(acc[3][0], a23.y, x.x); fma2(acc[3][1], a23.y, x.y);
            fma2(acc[4][0], a45.x, x.x); fma2(acc[4][1], a45.x, x.y);
            fma2(acc[5][0], a45.y, x.x); fma2(acc[5][1], a45.y, x.y);
            fma2(acc[6][0], a67.x, x.x); fma2(acc[6][1], a67.x, x.y);
            fma2(acc[7][0], a67.y, x.x); fma2(acc[7][1], a67.y, x.y);
        }
        __syncthreads();                 // nb_t dead; part2 aliases it
        ulonglong2* p2 = (ulonglong2*)sm;
        #pragma unroll
        for (int h = 0; h < NH; h++) {
            ulonglong2 v; v.x = acc[h][0]; v.y = acc[h][1];
            p2[h * 256 + q * 64 + c4] = v;
        }
    }
    __syncthreads();

    // ---- reduce partials over q, write ctx ----
    {
        const float4* p4 = (const float4*)sm;
        float4* cg = (float4*)(d_ctx + (long)b * 2048);
        #pragma unroll
        for (int k = 0; k < 2; k++) {
            int o = t + k * 256;            // h*64 + c4
            int h = o >> 6, c4o = o & 63;
            float4 r0 = p4[h * 256 + 0 * 64 + c4o];
            float4 r1 = p4[h * 256 + 1 * 64 + c4o];
            float4 r2 = p4[h * 256 + 2 * 64 + c4o];
            float4 r3 = p4[h * 256 + 3 * 64 + c4o];
            float4 r;
            r.x = (r0.x + r1.x) + (r2.x + r3.x);
            r.y = (r0.y + r1.y) + (r2.y + r3.y);
            r.z = (r0.z + r1.z) + (r2.z + r3.z);
            r.w = (r0.w + r1.w) + (r2.w + r3.w);
            cg[o] = r;
        }
    }
}

// ---------------- LayerNorm + ReLU (warp per row, float4) ----------------
__global__ void ln_relu_kernel(const float* __restrict__ g,
                               const float* __restrict__ be,
                               float* __restrict__ out) {
    const int b = blockIdx.x * 8 + (threadIdx.x >> 5);
    const int l = threadIdx.x & 31;
    const float4* yr = (const float4*)(d_y + (long)b * DM) + l * 2;
    float4 v0 = yr[0], v1 = yr[1];
    float s = v0.x + v0.y + v0.z + v0.w + v1.x + v1.y + v1.z + v1.w;
    #pragma unroll
    for (int o = 16; o; o >>= 1) s += __shfl_xor_sync(0xffffffffu, s, o);
    float mu = s * (1.f / 256.f);
    float vs = 0.f;
    {
        float d;
        d = v0.x - mu; vs += d * d;  d = v0.y - mu; vs += d * d;
        d = v0.z - mu; vs += d * d;  d = v0.w - mu; vs += d * d;
        d = v1.x - mu; vs += d * d;  d = v1.y - mu; vs += d * d;
        d = v1.z - mu; vs += d * d;  d = v1.w - mu; vs += d * d;
    }
    #pragma unroll
    for (int o = 16; o; o >>= 1) vs += __shfl_xor_sync(0xffffffffu, vs, o);
    float r = rsqrtf(vs * (1.f / 256.f) + 1e-5f);
    const float4* gp = (const float4*)g + l * 2;
    const float4* bp = (const float4*)be + l * 2;
    float4* op = (float4*)(out + (long)b * DM) + l * 2;
    float4 g0 = gp[0], g1 = gp[1], b0 = bp[0], b1 = bp[1];
    float4 o0, o1;
    o0.x = fmaxf((v0.x - mu) * r * g0.x + b0.x, 0.f);
    o0.y = fmaxf((v0.y - mu) * r * g0.y + b0.y, 0.f);
    o0.z = fmaxf((v0.z - mu) * r * g0.z + b0.z, 0.f);
    o0.w = fmaxf((v0.w - mu) * r * g0.w + b0.w, 0.f);
    o1.x = fmaxf((v1.x - mu) * r * g1.x + b1.x, 0.f);
    o1.y = fmaxf((v1.y - mu) * r * g1.y + b1.y, 0.f);
    o1.z = fmaxf((v1.z - mu) * r * g1.z + b1.z, 0.f);
    o1.w = fmaxf((v1.w - mu) * r * g1.w + b1.w, 0.f);
    op[0] = o0; op[1] = o1;
}

// ---------------- host launcher ----------------
extern "C" void kernel_launch(void* const* d_in, const int* in_sizes, int n_in,
                              void* d_out, int out_size) {
    const float* cde = (const float*)d_in[0];
    const float* nb  = (const float*)d_in[1];
    const unsigned int* et = (const unsigned int*)d_in[2];
    const float* Wq = (const float*)d_in[3];
    const float* bq = (const float*)d_in[4];
    const float* Wk = (const float*)d_in[5];
    const float* bk = (const float*)d_in[6];
    const float* Wv = (const float*)d_in[7];
    const float* bv = (const float*)d_in[8];
    const float* Wo = (const float*)d_in[9];
    const float* bo = (const float*)d_in[10];
    const float* ebt = (const float*)d_in[11];
    const float* Wf = (const float*)d_in[12];
    const float* bfv = (const float*)d_in[13];
    const float* lg = (const float*)d_in[14];
    const float* lb = (const float*)d_in[15];
    float* out = (float*)d_out;

    float *pQ, *pU, *pCtx, *pAtt, *pY, *pWkT, *pWoT, *pWc, *pB1;
    cudaGetSymbolAddress((void**)&pQ,   d_Q);
    cudaGetSymbolAddress((void**)&pU,   d_U);
    cudaGetSymbolAddress((void**)&pCtx, d_ctx);
    cudaGetSymbolAddress((void**)&pAtt, d_att);
    cudaGetSymbolAddress((void**)&pY,   d_y);
    cudaGetSymbolAddress((void**)&pWkT, d_WkT);
    cudaGetSymbolAddress((void**)&pWoT, d_WoT);
    cudaGetSymbolAddress((void**)&pWc,  d_Wc);
    cudaGetSymbolAddress((void**)&pB1,  d_b1);

    cudaFuncSetAttribute(attn_kernel,
                         cudaFuncAttributeMaxDynamicSharedMemorySize,
                         ATTN_SMEM_BYTES);

    // 1) prep (transposes + b1 + edge detect)
    prep_kernel<<<256, 256>>>(Wk, Wo, Wf, bo, bfv, et);
    // 2) Q = cde @ Wq^T + bq
    gemm2_kernel<64, 64, 8, 4><<<dim3(DM / 64, BATCH / 64, 1), 128>>>(
        cde, DM, 0, Wq, DM, 0, nullptr, 0, nullptr, 0,
        bq, 0, pQ, DM, 0, DM, DM, 1.f);
    // 3) U[b,h,:] = SCALE * Qh^T Wk_h
    gemm2_kernel<64, 64, 8, 4><<<dim3(DM / 64, BATCH / 64, NH), 128>>>(
        pQ, DM, HD, pWkT, HD, (long)DM * HD, nullptr, 0, nullptr, 0,
        nullptr, 0, pU, NH * DM, DM, HD, HD, SCALE);
    // 4) fused attention  (launch #4 -> ncu capture target)
    attn_kernel<<<BATCH, 256, ATTN_SMEM_BYTES>>>(nb, et, ebt, bk);
    // 5) Wc = Wf[:, :256] @ Wo
    gemm2_kernel<64, 64, 8, 4><<<dim3(DM / 64, DM / 64, 1), 128>>>(
        Wf, 2 * DM, 0, pWoT, DM, 0, nullptr, 0, nullptr, 0,
        nullptr, 0, pWc, DM, 0, DM, DM, 1.f);
    // 6) att[b, h*32+d] = Wv_h[d,:].ctx[b,h,:] + bv
    gemm2_kernel<128, 32, 8, 2><<<dim3(1, BATCH / 128, NH), 256>>>(
        pCtx, NH * DM, DM, Wv, DM, (long)HD * DM, nullptr, 0, nullptr, 0,
        bv, HD, pAtt, DM, HD, DM, DM, 1.f);
    // 7) y = att @ Wc^T + cde @ Wf[:,256:]^T + b1
    gemm2_kernel<64, 64, 8, 4><<<dim3(DM / 64, BATCH / 64, 1), 128>>>(
        pAtt, DM, 0, pWc, DM, 0, cde, DM, Wf + DM, 2 * DM,
        pB1, 0, pY, DM, 0, DM, 2 * DM, 1.f);
    // 8) LayerNorm + ReLU -> out
    ln_relu_kernel<<<BATCH / 8, 256>>>(lg, lb, out);
}

// round 9
// speedup vs baseline: 1.2811x; 1.1014x over previous
#include <cuda_runtime.h>
#include <cuda_bf16.h>
#include <math.h>

#define BATCH 4096
#define NNB   64
#define DM    256
#define NH    8
#define HD    32
#define SCALE 0.17677669529663687f   // 1/sqrt(32)

// ---------------- f32x2 packed helpers ----------------
__device__ __forceinline__ void fma2(unsigned long long& d,
                                     unsigned long long a,
                                     unsigned long long b) {
    asm("fma.rn.f32x2 %0, %1, %2, %0;" : "+l"(d) : "l"(a), "l"(b));
}
__device__ __forceinline__ float2 upk(unsigned long long v) {
    float2 r;
    asm("mov.b64 {%0, %1}, %2;" : "=f"(r.x), "=f"(r.y) : "l"(v));
    return r;
}

// ---------------- scratch ----------------
__device__ float d_Q  [BATCH * DM];
__device__ float d_U  [BATCH * NH * DM];
__device__ float d_ctx[BATCH * NH * DM];
__device__ float d_att[BATCH * DM];
__device__ float d_y  [BATCH * DM];
__device__ float d_WkT[NH * DM * HD];      // [h][c][d]
__device__ float d_WoT[DM * DM];
__device__ float d_Wc [DM * DM];
__device__ float d_b1 [DM];
__device__ unsigned int d_or = 0u;         // OR of odd words; 0 => int64

// ---------------- prep: transposes + b1 + edge-dtype detect ----------------
__global__ void prep_kernel(const float* __restrict__ Wk,
                            const float* __restrict__ Wo,
                            const float* __restrict__ Wf,
                            const float* __restrict__ bo,
                            const float* __restrict__ bfv,
                            const unsigned int* __restrict__ e32) {
    const int blk = blockIdx.x, t = threadIdx.x;
    const int i = blk * 256 + t;                 // 0..65535
    { int dd = i & 31, c = (i >> 5) & 255, h = i >> 13;
      d_WkT[i] = Wk[(h * HD + dd) * DM + c]; }
    { int j = i >> 8, m = i & 255;
      d_WoT[i] = Wo[m * DM + j]; }
    if (blk < 32) {
        int o = blk * 8 + (t >> 5), l = t & 31;
        float s = 0.f;
        #pragma unroll
        for (int m = l; m < DM; m += 32) s += Wf[o * 2 * DM + m] * bo[m];
        #pragma unroll
        for (int off = 16; off; off >>= 1) s += __shfl_xor_sync(0xffffffffu, s, off);
        if (l == 0) d_b1[o] = bfv[o] + s;
    }
    unsigned int acc = 0u;
    #pragma unroll
    for (int w = i; w < BATCH * NNB; w += 65536) acc |= e32[2 * w + 1];
    #pragma unroll
    for (int o = 16; o; o >>= 1) acc |= __shfl_xor_sync(0xffffffffu, acc, o);
    __shared__ unsigned int sOr;
    if (t == 0) sOr = 0u;
    __syncthreads();
    if ((t & 31) == 0 && acc) atomicOr(&sOr, acc);
    __syncthreads();
    if (t == 0 && sOr) atomicOr(&d_or, sOr);
}

// ---------------- double-buffered NT GEMM (plain FFMA, proven R4) -----------
template<int BM, int BN, int TM, int TN>
__global__ void gemm2_kernel(const float* __restrict__ A1, int lda1, long az1,
                             const float* __restrict__ B1, int ldb1, long bz1,
                             const float* __restrict__ A2, int lda2,
                             const float* __restrict__ B2, int ldb2,
                             const float* __restrict__ bias, long biasz,
                             float* __restrict__ C, int ldc, long cz,
                             int K1, int Ktot, float alpha) {
    constexpr int BK = 16;
    constexpr int NT = (BM / TM) * (BN / TN);
    constexpr int PAD = 4;
    constexpr int A4 = BM * BK / 4;
    constexpr int B4 = BN * BK / 4;
    constexpr int NA = (A4 + NT - 1) / NT;
    constexpr int NB = (B4 + NT - 1) / NT;

    __shared__ float As[2][BK][BM + PAD];
    __shared__ float Bs[2][BK][BN + PAD];

    const int tid = threadIdx.x;
    const int tx = tid % (BN / TN);
    const int ty = tid / (BN / TN);
    const int row0 = blockIdx.y * BM;
    const int col0 = blockIdx.x * BN;
    const int z = blockIdx.z;

    const float* A1g = A1 + (long)z * az1;
    const float* B1g = B1 + (long)z * bz1;
    float* Cg = C + (long)z * cz;
    const float* biasg = bias ? bias + (long)z * biasz : nullptr;

    float4 ra[NA], rb[NB];

    auto fetch = [&](int t) {
        int k0 = t * BK;
        const float *Ap, *Bp; int lda, ldb, k;
        if (k0 < K1) { Ap = A1g; lda = lda1; Bp = B1g; ldb = ldb1; k = k0; }
        else         { Ap = A2;  lda = lda2; Bp = B2;  ldb = ldb2; k = k0 - K1; }
        #pragma unroll
        for (int i = 0; i < NA; i++) {
            int f = tid + i * NT;
            if (f < A4) {
                int r = f >> 2, kq = f & 3;
                ra[i] = *reinterpret_cast<const float4*>(Ap + (long)(row0 + r) * lda + k + kq * 4);
            }
        }
        #pragma unroll
        for (int i = 0; i < NB; i++) {
            int f = tid + i * NT;
            if (f < B4) {
                int n = f >> 2, kq = f & 3;
                rb[i] = *reinterpret_cast<const float4*>(Bp + (long)(col0 + n) * ldb + k + kq * 4);
            }
        }
    };
    auto stage = [&](int buf) {
        #pragma unroll
        for (int i = 0; i < NA; i++) {
            int f = tid + i * NT;
            if (f < A4) {
                int r = f >> 2, kq = f & 3;
                As[buf][kq * 4 + 0][r] = ra[i].x;
                As[buf][kq * 4 + 1][r] = ra[i].y;
                As[buf][kq * 4 + 2][r] = ra[i].z;
                As[buf][kq * 4 + 3][r] = ra[i].w;
            }
        }
        #pragma unroll
        for (int i = 0; i < NB; i++) {
            int f = tid + i * NT;
            if (f < B4) {
                int n = f >> 2, kq = f & 3;
                Bs[buf][kq * 4 + 0][n] = rb[i].x;
                Bs[buf][kq * 4 + 1][n] = rb[i].y;
                Bs[buf][kq * 4 + 2][n] = rb[i].z;
                Bs[buf][kq * 4 + 3][n] = rb[i].w;
            }
        }
    };

    float acc[TM][TN];
    #pragma unroll
    for (int i = 0; i < TM; i++)
        #pragma unroll
        for (int j = 0; j < TN; j++) acc[i][j] = 0.f;

    fetch(0); stage(0); __syncthreads();
    const int ntiles = Ktot / BK;
    for (int t = 0; t < ntiles; t++) {
        int cur = t & 1;
        if (t + 1 < ntiles) fetch(t + 1);
        #pragma unroll
        for (int kk = 0; kk < BK; kk++) {
            float a[TM], b[TN];
            #pragma unroll
            for (int i = 0; i < TM; i++) a[i] = As[cur][kk][ty * TM + i];
            #pragma unroll
            for (int j = 0; j < TN; j++) b[j] = Bs[cur][kk][tx * TN + j];
            #pragma unroll
            for (int i = 0; i < TM; i++)
                #pragma unroll
                for (int j = 0; j < TN; j++) acc[i][j] += a[i] * b[j];
        }
        if (t + 1 < ntiles) stage(cur ^ 1);
        __syncthreads();
    }

    #pragma unroll
    for (int i = 0; i < TM; i++) {
        int r = row0 + ty * TM + i;
        #pragma unroll
        for (int j = 0; j < TN; j++) {
            int c = col0 + tx * TN + j;
            float v = alpha * acc[i][j];
            if (biasg) v += biasg[c];
            Cg[(long)r * ldc + c] = v;
        }
    }
}

// ---------------- fused attention v6 ----------------
// smem floats:
//   nb_t  [0, 16640)      transposed: slot c4 (0..63) x 65 float4 (n + pad)
//   u_s   [16640, 18688)  2048 fp32
//   part  [18688, 22784)  [h*512 + q8*64 + n]  (4096)
//   adup  [22784, 23808)  [n*16 + h*2 + {0,1}]
//   tbl   [23808, 23872)  [e*8 + h]
//   kb_s  [23872, 23880)
//   et_s  [23880, 23944)  ints
//   part2 (phase 2 only) aliases [0, 8192) floats over dead nb_t
#define U_S_OFF   16640
#define PART_OFF  18688
#define ADUP_OFF  22784
#define TBL_OFF   23808
#define KB_OFF    23872
#define ET_OFF    23880
#define ATTN_SMEM_BYTES (23944 * 4)

__global__ __launch_bounds__(256) void attn_kernel(
        const float* __restrict__ nb,
        const unsigned int* __restrict__ e32,
        const float* __restrict__ ebt,
        const float* __restrict__ bk) {
    extern __shared__ __align__(16) float sm[];
    float4* nbt  = (float4*)sm;
    float*  u_s  = sm + U_S_OFF;
    float*  part = sm + PART_OFF;
    float*  adup = sm + ADUP_OFF;
    float*  tbl  = sm + TBL_OFF;
    float*  kb_s = sm + KB_OFF;
    int*    et_s = (int*)(sm + ET_OFF);

    const int b = blockIdx.x;
    const int t = threadIdx.x;

    // ---- stage nb transposed, u, et, tbl, kbias ----
    const float4* nbg = (const float4*)(nb + (long)b * NNB * DM);
    #pragma unroll
    for (int i = 0; i < 16; i++) {
        int f = t + i * 256;
        int row = f >> 6, c4 = f & 63;
        nbt[c4 * 65 + row] = nbg[f];
    }
    const float4* ug = (const float4*)(d_U + (long)b * 2048);
    *reinterpret_cast<float4*>(u_s + t * 4)        = ug[t];
    *reinterpret_cast<float4*>(u_s + 1024 + t * 4) = ug[256 + t];
    if (t < NNB) {
        int v = (d_or == 0u) ? (int)e32[(long)b * (2 * NNB) + 2 * t]
                             : (int)e32[(long)b * NNB + t];
        et_s[t] = v;
        tbl[t] = ebt[t];                 // [e*8+h]
    }
    {
        const int w = t >> 5, l = t & 31;
        float s = d_Q[(long)b * DM + w * HD + l] * bk[w * HD + l];
        #pragma unroll
        for (int o = 16; o; o >>= 1) s += __shfl_xor_sync(0xffffffffu, s, o);
        if (l == 0) kb_s[w] = SCALE * s;
    }
    __syncthreads();

    // ---- phase 1: thread (n2 = t&31 -> {n2, n2+32}, q8 = t>>5), FFMA2 ----
    // Each u broadcast feeds 2 neighbors.
    {
        const int n2 = t & 31, q8 = t >> 5;
        unsigned long long accA[NH], accB[NH];
        #pragma unroll
        for (int h = 0; h < NH; h++) { accA[h] = 0ull; accB[h] = 0ull; }
        #pragma unroll
        for (int c4 = 0; c4 < 8; c4++) {             // 8 float4 chunks of c
            int slot = q8 * 8 + c4;
            ulonglong2 xA = *reinterpret_cast<const ulonglong2*>(nbt + slot * 65 + n2);
            ulonglong2 xB = *reinterpret_cast<const ulonglong2*>(nbt + slot * 65 + n2 + 32);
            #pragma unroll
            for (int h = 0; h < NH; h++) {
                ulonglong2 u = *reinterpret_cast<const ulonglong2*>(
                    u_s + h * DM + q8 * 32 + c4 * 4);   // warp-uniform 16B
                fma2(accA[h], u.x, xA.x);
                fma2(accA[h], u.y, xA.y);
                fma2(accB[h], u.x, xB.x);
                fma2(accB[h], u.y, xB.y);
            }
        }
        #pragma unroll
        for (int h = 0; h < NH; h++) {
            float2 vA = upk(accA[h]);
            float2 vB = upk(accB[h]);
            part[h * 512 + q8 * 64 + n2]      = vA.x + vA.y;
            part[h * 512 + q8 * 64 + n2 + 32] = vB.x + vB.y;
        }
    }
    __syncthreads();

    // ---- softmax with inline combine: warp w = head w; writes adup pairs ----
    {
        const int w = t >> 5, l = t & 31;
        float lg0 = kb_s[w] + tbl[et_s[l] * NH + w];
        float lg1 = kb_s[w] + tbl[et_s[l + 32] * NH + w];
        #pragma unroll
        for (int q = 0; q < 8; q++) {
            lg0 += part[w * 512 + q * 64 + l];
            lg1 += part[w * 512 + q * 64 + l + 32];
        }
        float m = fmaxf(lg0, lg1);
        #pragma unroll
        for (int o = 16; o; o >>= 1) m = fmaxf(m, __shfl_xor_sync(0xffffffffu, m, o));
        float e0 = __expf(lg0 - m), e1 = __expf(lg1 - m);
        float s = e0 + e1;
        #pragma unroll
        for (int o = 16; o; o >>= 1) s += __shfl_xor_sync(0xffffffffu, s, o);
        float inv = 1.f / s;
        float a0 = e0 * inv, a1 = e1 * inv;
        adup[l * 16 + w * 2]            = a0;
        adup[l * 16 + w * 2 + 1]        = a0;
        adup[(l + 32) * 16 + w * 2]     = a1;
        adup[(l + 32) * 16 + w * 2 + 1] = a1;
    }
    __syncthreads();

    // ---- phase 2: thread (c4 = t&63, q = t>>6) rows {q+4j}, all 8 heads ----
    {
        const int c4 = t & 63, q = t >> 6;
        unsigned long long acc[NH][2];
        #pragma unroll
        for (int h = 0; h < NH; h++) { acc[h][0] = 0ull; acc[h][1] = 0ull; }
        #pragma unroll
        for (int j = 0; j < 16; j++) {
            int n = q + 4 * j;
            ulonglong2 x = *reinterpret_cast<const ulonglong2*>(nbt + c4 * 65 + n);
            const ulonglong2* ap = reinterpret_cast<const ulonglong2*>(adup + n * 16);
            ulonglong2 a01 = ap[0], a23 = ap[1], a45 = ap[2], a67 = ap[3];
            fma2(acc[0][0], a01.x, x.x); fma2(acc[0][1], a01.x, x.y);
            fma2(acc[1][0], a01.y, x.x); fma2(acc[1][1], a01.y, x.y);
            fma2(acc[2][0], a23.x, x.x); fma2(acc[2][1], a23.x, x.y);
            fma2(acc[3][0], a23.y, x.x); fma2(acc[3][1], a23.y, x.y);
            fma2(acc[4][0], a45.x, x.x); fma2(acc[4][1], a45.x, x.y);
            fma2(acc[5][0], a45.y, x.x); fma2(acc[5][1], a45.y, x.y);
            fma2(acc[6][0], a67.x, x.x); fma2(acc[6][1], a67.x, x.y);
            fma2(acc[7][0], a67.y, x.x); fma2(acc[7][1], a67.y, x.y);
        }
        __syncthreads();                 // nb_t dead; part2 aliases it
        ulonglong2* p2 = (ulonglong2*)sm;
        #pragma unroll
        for (int h = 0; h < NH; h++) {
            ulonglong2 v; v.x = acc[h][0]; v.y = acc[h][1];
            p2[h * 256 + q * 64 + c4] = v;
        }
    }
    __syncthreads();

    // ---- reduce partials over q, write ctx ----
    {
        const float4* p4 = (const float4*)sm;
        float4* cg = (float4*)(d_ctx + (long)b * 2048);
        #pragma unroll
        for (int k = 0; k < 2; k++) {
            int o = t + k * 256;            // h*64 + c4
            int h = o >> 6, c4o = o & 63;
            float4 r0 = p4[h * 256 + 0 * 64 + c4o];
            float4 r1 = p4[h * 256 + 1 * 64 + c4o];
            float4 r2 = p4[h * 256 + 2 * 64 + c4o];
            float4 r3 = p4[h * 256 + 3 * 64 + c4o];
            float4 r;
            r.x = (r0.x + r1.x) + (r2.x + r3.x);
            r.y = (r0.y + r1.y) + (r2.y + r3.y);
            r.z = (r0.z + r1.z) + (r2.z + r3.z);
            r.w = (r0.w + r1.w) + (r2.w + r3.w);
            cg[o] = r;
        }
    }
}

// ---------------- LayerNorm + ReLU (warp per row, float4) ----------------
__global__ void ln_relu_kernel(const float* __restrict__ g,
                               const float* __restrict__ be,
                               float* __restrict__ out) {
    const int b = blockIdx.x * 8 + (threadIdx.x >> 5);
    const int l = threadIdx.x & 31;
    const float4* yr = (const float4*)(d_y + (long)b * DM) + l * 2;
    float4 v0 = yr[0], v1 = yr[1];
    float s = v0.x + v0.y + v0.z + v0.w + v1.x + v1.y + v1.z + v1.w;
    #pragma unroll
    for (int o = 16; o; o >>= 1) s += __shfl_xor_sync(0xffffffffu, s, o);
    float mu = s * (1.f / 256.f);
    float vs = 0.f;
    {
        float d;
        d = v0.x - mu; vs += d * d;  d = v0.y - mu; vs += d * d;
        d = v0.z - mu; vs += d * d;  d = v0.w - mu; vs += d * d;
        d = v1.x - mu; vs += d * d;  d = v1.y - mu; vs += d * d;
        d = v1.z - mu; vs += d * d;  d = v1.w - mu; vs += d * d;
    }
    #pragma unroll
    for (int o = 16; o; o >>= 1) vs += __shfl_xor_sync(0xffffffffu, vs, o);
    float r = rsqrtf(vs * (1.f / 256.f) + 1e-5f);
    const float4* gp = (const float4*)g + l * 2;
    const float4* bp = (const float4*)be + l * 2;
    float4* op = (float4*)(out + (long)b * DM) + l * 2;
    float4 g0 = gp[0], g1 = gp[1], b0 = bp[0], b1 = bp[1];
    float4 o0, o1;
    o0.x = fmaxf((v0.x - mu) * r * g0.x + b0.x, 0.f);
    o0.y = fmaxf((v0.y - mu) * r * g0.y + b0.y, 0.f);
    o0.z = fmaxf((v0.z - mu) * r * g0.z + b0.z, 0.f);
    o0.w = fmaxf((v0.w - mu) * r * g0.w + b0.w, 0.f);
    o1.x = fmaxf((v1.x - mu) * r * g1.x + b1.x, 0.f);
    o1.y = fmaxf((v1.y - mu) * r * g1.y + b1.y, 0.f);
    o1.z = fmaxf((v1.z - mu) * r * g1.z + b1.z, 0.f);
    o1.w = fmaxf((v1.w - mu) * r * g1.w + b1.w, 0.f);
    op[0] = o0; op[1] = o1;
}

// ---------------- host launcher ----------------
extern "C" void kernel_launch(void* const* d_in, const int* in_sizes, int n_in,
                              void* d_out, int out_size) {
    const float* cde = (const float*)d_in[0];
    const float* nb  = (const float*)d_in[1];
    const unsigned int* et = (const unsigned int*)d_in[2];
    const float* Wq = (const float*)d_in[3];
    const float* bq = (const float*)d_in[4];
    const float* Wk = (const float*)d_in[5];
    const float* bk = (const float*)d_in[6];
    const float* Wv = (const float*)d_in[7];
    const float* bv = (const float*)d_in[8];
    const float* Wo = (const float*)d_in[9];
    const float* bo = (const float*)d_in[10];
    const float* ebt = (const float*)d_in[11];
    const float* Wf = (const float*)d_in[12];
    const float* bfv = (const float*)d_in[13];
    const float* lg = (const float*)d_in[14];
    const float* lb = (const float*)d_in[15];
    float* out = (float*)d_out;

    float *pQ, *pU, *pCtx, *pAtt, *pY, *pWkT, *pWoT, *pWc, *pB1;
    cudaGetSymbolAddress((void**)&pQ,   d_Q);
    cudaGetSymbolAddress((void**)&pU,   d_U);
    cudaGetSymbolAddress((void**)&pCtx, d_ctx);
    cudaGetSymbolAddress((void**)&pAtt, d_att);
    cudaGetSymbolAddress((void**)&pY,   d_y);
    cudaGetSymbolAddress((void**)&pWkT, d_WkT);
    cudaGetSymbolAddress((void**)&pWoT, d_WoT);
    cudaGetSymbolAddress((void**)&pWc,  d_Wc);
    cudaGetSymbolAddress((void**)&pB1,  d_b1);

    cudaFuncSetAttribute(attn_kernel,
                         cudaFuncAttributeMaxDynamicSharedMemorySize,
                         ATTN_SMEM_BYTES);

    // 1) prep (transposes + b1 + edge detect)
    prep_kernel<<<256, 256>>>(Wk, Wo, Wf, bo, bfv, et);
    // 2) Q = cde @ Wq^T + bq
    gemm2_kernel<64, 64, 8, 4><<<dim3(DM / 64, BATCH / 64, 1), 128>>>(
        cde, DM, 0, Wq, DM, 0, nullptr, 0, nullptr, 0,
        bq, 0, pQ, DM, 0, DM, DM, 1.f);
    // 3) U[b,h,:] = SCALE * Qh^T Wk_h
    gemm2_kernel<64, 64, 8, 4><<<dim3(DM / 64, BATCH / 64, NH), 128>>>(
        pQ, DM, HD, pWkT, HD, (long)DM * HD, nullptr, 0, nullptr, 0,
        nullptr, 0, pU, NH * DM, DM, HD, HD, SCALE);
    // 4) fused attention  (launch #4 -> ncu capture target)
    attn_kernel<<<BATCH, 256, ATTN_SMEM_BYTES>>>(nb, et, ebt, bk);
    // 5) Wc = Wf[:, :256] @ Wo
    gemm2_kernel<64, 64, 8, 4><<<dim3(DM / 64, DM / 64, 1), 128>>>(
        Wf, 2 * DM, 0, pWoT, DM, 0, nullptr, 0, nullptr, 0,
        nullptr, 0, pWc, DM, 0, DM, DM, 1.f);
    // 6) att[b, h*32+d] = Wv_h[d,:].ctx[b,h,:] + bv
    gemm2_kernel<128, 32, 8, 2><<<dim3(1, BATCH / 128, NH), 256>>>(
        pCtx, NH * DM, DM, Wv, DM, (long)HD * DM, nullptr, 0, nullptr, 0,
        bv, HD, pAtt, DM, HD, DM, DM, 1.f);
    // 7) y = att @ Wc^T + cde @ Wf[:,256:]^T + b1
    gemm2_kernel<64, 64, 8, 4><<<dim3(DM / 64, BATCH / 64, 1), 128>>>(
        pAtt, DM, 0, pWc, DM, 0, cde, DM, Wf + DM, 2 * DM,
        pB1, 0, pY, DM, 0, DM, 2 * DM, 1.f);
    // 8) LayerNorm + ReLU -> out
    ln_relu_kernel<<<BATCH / 8, 256>>>(lg, lb, out);
}